// round 1
// baseline (speedup 1.0000x reference)
#include <cuda_runtime.h>
#include <math.h>

#define EPSF 1e-5f

constexpr int B_  = 2, T_ = 16, S_ = 256, C_ = 1024, H_ = 16, HD_ = 64;
constexpr int R_  = B_ * T_ * S_;   // 8192 tokens
constexpr int HID_ = 4 * C_;        // 4096
constexpr float SCALE_ = 8.0f / 64.0f;

// ---- scratch (device globals; no runtime allocation allowed) ----
__device__ float g_xbuf[R_ * C_];
__device__ float g_xln [R_ * C_];
__device__ float g_qkv [R_ * 3 * C_];
__device__ float g_attn[R_ * C_];
__device__ float g_xt  [R_ * C_];
__device__ float g_h   [R_ * HID_];

// ============================================================
// LayerNorm over C=1024, one block (256 threads) per row
// ============================================================
__global__ void ln_kernel(const float* __restrict__ in, float* __restrict__ out,
                          const float* __restrict__ w, const float* __restrict__ b)
{
    const int row = blockIdx.x, tid = threadIdx.x;
    const float4 xv = reinterpret_cast<const float4*>(in + (size_t)row * 1024)[tid];
    float s  = xv.x + xv.y + xv.z + xv.w;
    float ss = xv.x*xv.x + xv.y*xv.y + xv.z*xv.z + xv.w*xv.w;
    __shared__ float sb[32], ssb[32];
    const int lane = tid & 31, wid = tid >> 5;
    #pragma unroll
    for (int o = 16; o; o >>= 1) {
        s  += __shfl_xor_sync(0xffffffffu, s,  o);
        ss += __shfl_xor_sync(0xffffffffu, ss, o);
    }
    if (lane == 0) { sb[wid] = s; ssb[wid] = ss; }
    __syncthreads();
    if (tid == 0) {
        float ts = 0.f, tss = 0.f;
        #pragma unroll
        for (int i = 0; i < 8; i++) { ts += sb[i]; tss += ssb[i]; }
        float mean = ts * (1.f / 1024.f);
        sb[0]  = mean;
        ssb[0] = rsqrtf(tss * (1.f / 1024.f) - mean * mean + EPSF);
    }
    __syncthreads();
    const float mean = sb[0], rstd = ssb[0];
    const float4 wv = reinterpret_cast<const float4*>(w)[tid];
    const float4 bv = reinterpret_cast<const float4*>(b)[tid];
    float4 o;
    o.x = (xv.x - mean) * rstd * wv.x + bv.x;
    o.y = (xv.y - mean) * rstd * wv.y + bv.y;
    o.z = (xv.z - mean) * rstd * wv.z + bv.z;
    o.w = (xv.w - mean) * rstd * wv.w + bv.w;
    reinterpret_cast<float4*>(out + (size_t)row * 1024)[tid] = o;
}

// ============================================================
// Per-head LN (hd=64) on q and k slices of the qkv buffer.
// One warp per 64-vector; q additionally scaled by SCALE.
// ============================================================
__global__ void headln_kernel(float* __restrict__ qkv, const float* __restrict__ w,
                              const float* __restrict__ b, float qscale)
{
    const int gw   = (blockIdx.x * blockDim.x + threadIdx.x) >> 5;
    const int lane = threadIdx.x & 31;
    const int r     = gw >> 5;        // row
    const int rem   = gw & 31;        // 2 * 16 vectors per row
    const int which = rem >> 4;       // 0 = q, 1 = k
    const int h     = rem & 15;
    float* p = qkv + (size_t)r * 3072 + which * 1024 + h * 64;
    const float v0 = p[lane], v1 = p[lane + 32];
    float s = v0 + v1, ss = v0*v0 + v1*v1;
    #pragma unroll
    for (int o = 16; o; o >>= 1) {
        s  += __shfl_xor_sync(0xffffffffu, s,  o);
        ss += __shfl_xor_sync(0xffffffffu, ss, o);
    }
    const float mean = s * (1.f / 64.f);
    const float rstd = rsqrtf(ss * (1.f / 64.f) - mean * mean + EPSF);
    const float sc = which ? 1.f : qscale;
    p[lane]      = ((v0 - mean) * rstd * w[lane]      + b[lane])      * sc;
    p[lane + 32] = ((v1 - mean) * rstd * w[lane + 32] + b[lane + 32]) * sc;
}

// ============================================================
// Attention: one block per (batch, head). K/V staged in SMEM,
// one thread per query row, two-pass streaming softmax.
// q is already LN'd and pre-scaled; k already LN'd.
// ============================================================
template<int N>
__global__ void attn_kernel(const float* __restrict__ qkv, float* __restrict__ out)
{
    extern __shared__ float sm[];
    float* Ks = sm;
    float* Vs = sm + N * 64;
    const int bh = blockIdx.x;
    const int h = bh & 15;
    const int batch = bh >> 4;
    const float* base = qkv + (size_t)batch * N * 3072;
    const int tid = threadIdx.x;

    for (int idx = tid; idx < N * 16; idx += N) {
        const int j = idx >> 4, d4 = idx & 15;
        const float4* kp = reinterpret_cast<const float4*>(base + (size_t)j * 3072 + 1024 + h * 64);
        const float4* vp = reinterpret_cast<const float4*>(base + (size_t)j * 3072 + 2048 + h * 64);
        reinterpret_cast<float4*>(Ks + j * 64)[d4] = kp[d4];
        reinterpret_cast<float4*>(Vs + j * 64)[d4] = vp[d4];
    }
    __syncthreads();

    float4 q[16];
    const float4* qp = reinterpret_cast<const float4*>(base + (size_t)tid * 3072 + h * 64);
    #pragma unroll
    for (int d = 0; d < 16; d++) q[d] = qp[d];

    float m = -1e30f;
    for (int j = 0; j < N; j++) {
        const float4* kr = reinterpret_cast<const float4*>(Ks + j * 64);
        float s = 0.f;
        #pragma unroll
        for (int d = 0; d < 16; d++) {
            const float4 kv = kr[d];
            s += q[d].x*kv.x + q[d].y*kv.y + q[d].z*kv.z + q[d].w*kv.w;
        }
        m = fmaxf(m, s);
    }

    float4 acc[16];
    #pragma unroll
    for (int d = 0; d < 16; d++) acc[d] = make_float4(0.f, 0.f, 0.f, 0.f);
    float sum = 0.f;
    for (int j = 0; j < N; j++) {
        const float4* kr = reinterpret_cast<const float4*>(Ks + j * 64);
        float s = 0.f;
        #pragma unroll
        for (int d = 0; d < 16; d++) {
            const float4 kv = kr[d];
            s += q[d].x*kv.x + q[d].y*kv.y + q[d].z*kv.z + q[d].w*kv.w;
        }
        const float e = __expf(s - m);
        sum += e;
        const float4* vr = reinterpret_cast<const float4*>(Vs + j * 64);
        #pragma unroll
        for (int d = 0; d < 16; d++) {
            const float4 vv = vr[d];
            acc[d].x += e * vv.x; acc[d].y += e * vv.y;
            acc[d].z += e * vv.z; acc[d].w += e * vv.w;
        }
    }
    const float inv = 1.f / sum;
    float4* op = reinterpret_cast<float4*>(out + ((size_t)batch * N + tid) * 1024 + h * 64);
    #pragma unroll
    for (int d = 0; d < 16; d++)
        op[d] = make_float4(acc[d].x * inv, acc[d].y * inv, acc[d].z * inv, acc[d].w * inv);
}

// ============================================================
// (B,T,S,C) <-> (B,S,T,C) row permutation, full-row float4 copy
// ============================================================
__global__ void permute_kernel(const float* __restrict__ src, float* __restrict__ dst, int fwd)
{
    const int rt = blockIdx.x;
    int in_row;
    if (fwd) {  // dst[(b*S+s)*T+t] = src[(b*T+t)*S+s]
        const int t = rt & 15;  const int bs = rt >> 4;
        const int s = bs & 255; const int b  = bs >> 8;
        in_row = (b * 16 + t) * 256 + s;
    } else {    // dst[(b*T+t)*S+s] = src[(b*S+s)*T+t]
        const int s = rt & 255; const int bt = rt >> 8;
        const int t = bt & 15;  const int b  = bt >> 4;
        in_row = (b * 256 + s) * 16 + t;
    }
    const float4* sp = reinterpret_cast<const float4*>(src + (size_t)in_row * 1024);
    float4* dp = reinterpret_cast<float4*>(dst + (size_t)rt * 1024);
    dp[threadIdx.x] = sp[threadIdx.x];
}

// ============================================================
// SGEMM: C = A[M,K] @ B[K,N] (+bias)(+resid)(+gelu)
// BM=BN=128, BK=8, 256 threads, 8x8 microtile per thread
// All of M,N div by 128; K div by 8.
// ============================================================
template<bool GELU>
__global__ __launch_bounds__(256) void gemm_kernel(
    const float* __restrict__ A, const float* __restrict__ Bm,
    float* __restrict__ Cm, const float* __restrict__ bias,
    const float* __restrict__ resid, int M, int N, int K)
{
    __shared__ float As[8][128];
    __shared__ float Bs[8][128];
    const int bx = blockIdx.x, by = blockIdx.y;
    const int tid = threadIdx.x;
    const int tx = tid & 15, ty = tid >> 4;

    const float* Ab = A  + (size_t)by * 128 * K;
    const float* Bb = Bm + (size_t)bx * 128;

    const int a_row = tid >> 1;
    const int a_k   = (tid & 1) * 4;
    const int b_k   = tid >> 5;
    const int b_col = (tid & 31) * 4;

    float acc[8][8];
    #pragma unroll
    for (int i = 0; i < 8; i++)
        #pragma unroll
        for (int j = 0; j < 8; j++) acc[i][j] = 0.f;

    for (int k0 = 0; k0 < K; k0 += 8) {
        const float4 av = *reinterpret_cast<const float4*>(Ab + (size_t)a_row * K + k0 + a_k);
        As[a_k + 0][a_row] = av.x; As[a_k + 1][a_row] = av.y;
        As[a_k + 2][a_row] = av.z; As[a_k + 3][a_row] = av.w;
        const float4 bv = *reinterpret_cast<const float4*>(Bb + (size_t)(k0 + b_k) * N + b_col);
        *reinterpret_cast<float4*>(&Bs[b_k][b_col]) = bv;
        __syncthreads();
        #pragma unroll
        for (int kk = 0; kk < 8; kk++) {
            float a[8], b[8];
            *reinterpret_cast<float4*>(a)     = *reinterpret_cast<const float4*>(&As[kk][ty * 8]);
            *reinterpret_cast<float4*>(a + 4) = *reinterpret_cast<const float4*>(&As[kk][ty * 8 + 4]);
            *reinterpret_cast<float4*>(b)     = *reinterpret_cast<const float4*>(&Bs[kk][tx * 8]);
            *reinterpret_cast<float4*>(b + 4) = *reinterpret_cast<const float4*>(&Bs[kk][tx * 8 + 4]);
            #pragma unroll
            for (int i = 0; i < 8; i++)
                #pragma unroll
                for (int j = 0; j < 8; j++)
                    acc[i][j] += a[i] * b[j];
        }
        __syncthreads();
    }

    const int col0 = bx * 128 + tx * 8;
    #pragma unroll
    for (int i = 0; i < 8; i++) {
        const int row = by * 128 + ty * 8 + i;
        float* cp = Cm + (size_t)row * N + col0;
        const float* rp = resid ? resid + (size_t)row * N + col0 : nullptr;
        #pragma unroll
        for (int j4 = 0; j4 < 8; j4 += 4) {
            float t0 = acc[i][j4], t1 = acc[i][j4 + 1], t2 = acc[i][j4 + 2], t3 = acc[i][j4 + 3];
            if (bias) {
                t0 += bias[col0 + j4];     t1 += bias[col0 + j4 + 1];
                t2 += bias[col0 + j4 + 2]; t3 += bias[col0 + j4 + 3];
            }
            if (rp) { t0 += rp[j4]; t1 += rp[j4 + 1]; t2 += rp[j4 + 2]; t3 += rp[j4 + 3]; }
            if (GELU) {
                t0 = 0.5f * t0 * (1.f + erff(t0 * 0.70710678f));
                t1 = 0.5f * t1 * (1.f + erff(t1 * 0.70710678f));
                t2 = 0.5f * t2 * (1.f + erff(t2 * 0.70710678f));
                t3 = 0.5f * t3 * (1.f + erff(t3 * 0.70710678f));
            }
            float4 v; v.x = t0; v.y = t1; v.z = t2; v.w = t3;
            *reinterpret_cast<float4*>(cp + j4) = v;
        }
    }
}

// ============================================================
extern "C" void kernel_launch(void* const* d_in, const int* /*in_sizes*/, int /*n_in*/,
                              void* d_out, int /*out_size*/)
{
    const float* x        = (const float*)d_in[0];
    const float* ns_w     = (const float*)d_in[1];
    const float* ns_b     = (const float*)d_in[2];
    const float* nt_w     = (const float*)d_in[3];
    const float* nt_b     = (const float*)d_in[4];
    const float* nm_w     = (const float*)d_in[5];
    const float* nm_b     = (const float*)d_in[6];
    const float* s_qkv    = (const float*)d_in[7];
    const float* s_qkn_w  = (const float*)d_in[8];
    const float* s_qkn_b  = (const float*)d_in[9];
    const float* s_proj_w = (const float*)d_in[10];
    const float* s_proj_b = (const float*)d_in[11];
    const float* t_qkv    = (const float*)d_in[12];
    const float* t_qkn_w  = (const float*)d_in[13];
    const float* t_qkn_b  = (const float*)d_in[14];
    const float* t_proj_w = (const float*)d_in[15];
    const float* t_proj_b = (const float*)d_in[16];
    const float* fc1_w    = (const float*)d_in[17];
    const float* fc1_b    = (const float*)d_in[18];
    const float* fc2_w    = (const float*)d_in[19];
    const float* fc2_b    = (const float*)d_in[20];
    float* out = (float*)d_out;

    float *xbuf, *xln, *qkv, *attn, *xt, *hbuf;
    cudaGetSymbolAddress((void**)&xbuf, g_xbuf);
    cudaGetSymbolAddress((void**)&xln,  g_xln);
    cudaGetSymbolAddress((void**)&qkv,  g_qkv);
    cudaGetSymbolAddress((void**)&attn, g_attn);
    cudaGetSymbolAddress((void**)&xt,   g_xt);
    cudaGetSymbolAddress((void**)&hbuf, g_h);

    cudaFuncSetAttribute(attn_kernel<256>, cudaFuncAttributeMaxDynamicSharedMemorySize,
                         256 * 64 * 2 * (int)sizeof(float));

    const int hl_blocks = (R_ * 2 * H_) / 8;  // 8 warps / block

    // ---- spatial attention block ----
    ln_kernel<<<R_, 256>>>(x, xln, ns_w, ns_b);
    gemm_kernel<false><<<dim3(24, 64), 256>>>(xln, s_qkv, qkv, nullptr, nullptr, R_, 3072, 1024);
    headln_kernel<<<hl_blocks, 256>>>(qkv, s_qkn_w, s_qkn_b, SCALE_);
    attn_kernel<256><<<B_ * T_ * H_, 256, 256 * 64 * 2 * sizeof(float)>>>(qkv, attn);
    gemm_kernel<false><<<dim3(8, 64), 256>>>(attn, s_proj_w, xbuf, s_proj_b, x, R_, 1024, 1024);

    // ---- temporal attention block ----
    permute_kernel<<<R_, 256>>>(xbuf, xt, 1);
    ln_kernel<<<R_, 256>>>(xt, xln, nt_w, nt_b);
    gemm_kernel<false><<<dim3(24, 64), 256>>>(xln, t_qkv, qkv, nullptr, nullptr, R_, 3072, 1024);
    headln_kernel<<<hl_blocks, 256>>>(qkv, t_qkn_w, t_qkn_b, SCALE_);
    attn_kernel<16><<<B_ * S_ * H_, 16, 16 * 64 * 2 * sizeof(float)>>>(qkv, attn);
    gemm_kernel<false><<<dim3(8, 64), 256>>>(attn, t_proj_w, xln, t_proj_b, xt, R_, 1024, 1024);
    permute_kernel<<<R_, 256>>>(xln, xbuf, 0);

    // ---- MLP ----
    ln_kernel<<<R_, 256>>>(xbuf, xln, nm_w, nm_b);
    gemm_kernel<true ><<<dim3(32, 64), 256>>>(xln, fc1_w, hbuf, fc1_b, nullptr, R_, 4096, 1024);
    gemm_kernel<false><<<dim3(8, 64), 256>>>(hbuf, fc2_w, out, fc2_b, xbuf, R_, 1024, 4096);
}

// round 3
// speedup vs baseline: 2.8766x; 2.8766x over previous
#include <cuda_runtime.h>
#include <cstdint>
#include <math.h>

#define EPSF 1e-5f

constexpr int B_  = 2, T_ = 16, S_ = 256, C_ = 1024, H_ = 16;
constexpr int R_  = B_ * T_ * S_;   // 8192 tokens
constexpr int HID_ = 4 * C_;        // 4096
constexpr float SCALE_ = 8.0f / 64.0f;

// ---- scratch (device globals; no runtime allocation allowed) ----
__device__ float g_xbuf[R_ * C_];
__device__ float g_xln [R_ * C_];
__device__ float g_qkv [R_ * 3 * C_];
__device__ float g_attn[R_ * C_];
__device__ float g_xt  [R_ * C_];
__device__ float g_h   [R_ * HID_];
// transposed (tf32-rounded) weights, [N,K] row-major
__device__ float g_wt_sqkv [3 * C_ * C_];
__device__ float g_wt_sproj[C_ * C_];
__device__ float g_wt_tqkv [3 * C_ * C_];
__device__ float g_wt_tproj[C_ * C_];
__device__ float g_wt_fc1  [HID_ * C_];
__device__ float g_wt_fc2  [C_ * HID_];

__device__ __forceinline__ uint32_t smem_u32(const void* p) {
    uint32_t a;
    asm("{ .reg .u64 t; cvta.to.shared.u64 t, %1; cvt.u32.u64 %0, t; }" : "=r"(a) : "l"(p));
    return a;
}
__device__ __forceinline__ float to_tf32(float x) {
    float r;
    asm("cvt.rna.tf32.f32 %0, %1;" : "=f"(r) : "f"(x));
    return r;
}
__device__ __forceinline__ void mma_tf32(float c[4], const uint32_t a[4], const uint32_t b[2]) {
    asm volatile("mma.sync.aligned.m16n8k8.row.col.f32.tf32.tf32.f32 "
        "{%0,%1,%2,%3}, {%4,%5,%6,%7}, {%8,%9}, {%0,%1,%2,%3};"
        : "+f"(c[0]), "+f"(c[1]), "+f"(c[2]), "+f"(c[3])
        : "r"(a[0]), "r"(a[1]), "r"(a[2]), "r"(a[3]), "r"(b[0]), "r"(b[1]));
}

// ============================================================
// Weight transpose + tf32 round: in [K,N] -> out [N,K]
// ============================================================
__global__ void transpose_w(const float* __restrict__ in, float* __restrict__ out,
                            int K, int N)
{
    __shared__ float t[32][33];
    const int n0 = blockIdx.x * 32, k0 = blockIdx.y * 32;
    const int x = threadIdx.x, y = threadIdx.y;
    #pragma unroll
    for (int i = 0; i < 32; i += 8)
        t[y + i][x] = in[(size_t)(k0 + y + i) * N + n0 + x];
    __syncthreads();
    #pragma unroll
    for (int i = 0; i < 32; i += 8)
        out[(size_t)(n0 + y + i) * K + k0 + x] = to_tf32(t[x][y + i]);
}

// ============================================================
// LayerNorm over C=1024 (tf32-rounded output: feeds GEMM A)
// ============================================================
__global__ void ln_kernel(const float* __restrict__ in, float* __restrict__ out,
                          const float* __restrict__ w, const float* __restrict__ b)
{
    const int row = blockIdx.x, tid = threadIdx.x;
    const float4 xv = reinterpret_cast<const float4*>(in + (size_t)row * 1024)[tid];
    float s  = xv.x + xv.y + xv.z + xv.w;
    float ss = xv.x*xv.x + xv.y*xv.y + xv.z*xv.z + xv.w*xv.w;
    __shared__ float sb[32], ssb[32];
    const int lane = tid & 31, wid = tid >> 5;
    #pragma unroll
    for (int o = 16; o; o >>= 1) {
        s  += __shfl_xor_sync(0xffffffffu, s,  o);
        ss += __shfl_xor_sync(0xffffffffu, ss, o);
    }
    if (lane == 0) { sb[wid] = s; ssb[wid] = ss; }
    __syncthreads();
    if (tid == 0) {
        float ts = 0.f, tss = 0.f;
        #pragma unroll
        for (int i = 0; i < 8; i++) { ts += sb[i]; tss += ssb[i]; }
        float mean = ts * (1.f / 1024.f);
        sb[0]  = mean;
        ssb[0] = rsqrtf(tss * (1.f / 1024.f) - mean * mean + EPSF);
    }
    __syncthreads();
    const float mean = sb[0], rstd = ssb[0];
    const float4 wv = reinterpret_cast<const float4*>(w)[tid];
    const float4 bv = reinterpret_cast<const float4*>(b)[tid];
    float4 o;
    o.x = to_tf32((xv.x - mean) * rstd * wv.x + bv.x);
    o.y = to_tf32((xv.y - mean) * rstd * wv.y + bv.y);
    o.z = to_tf32((xv.z - mean) * rstd * wv.z + bv.z);
    o.w = to_tf32((xv.w - mean) * rstd * wv.w + bv.w);
    reinterpret_cast<float4*>(out + (size_t)row * 1024)[tid] = o;
}

// ============================================================
// Per-head LN (hd=64) on q and k slices of the qkv buffer.
// ============================================================
__global__ void headln_kernel(float* __restrict__ qkv, const float* __restrict__ w,
                              const float* __restrict__ b, float qscale)
{
    const int gw   = (blockIdx.x * blockDim.x + threadIdx.x) >> 5;
    const int lane = threadIdx.x & 31;
    const int r     = gw >> 5;
    const int rem   = gw & 31;
    const int which = rem >> 4;
    const int h     = rem & 15;
    float* p = qkv + (size_t)r * 3072 + which * 1024 + h * 64;
    const float v0 = p[lane], v1 = p[lane + 32];
    float s = v0 + v1, ss = v0*v0 + v1*v1;
    #pragma unroll
    for (int o = 16; o; o >>= 1) {
        s  += __shfl_xor_sync(0xffffffffu, s,  o);
        ss += __shfl_xor_sync(0xffffffffu, ss, o);
    }
    const float mean = s * (1.f / 64.f);
    const float rstd = rsqrtf(ss * (1.f / 64.f) - mean * mean + EPSF);
    const float sc = which ? 1.f : qscale;
    p[lane]      = ((v0 - mean) * rstd * w[lane]      + b[lane])      * sc;
    p[lane + 32] = ((v1 - mean) * rstd * w[lane + 32] + b[lane + 32]) * sc;
}

// ============================================================
// Attention (unchanged; output tf32-rounded, feeds proj GEMM A)
// ============================================================
template<int N>
__global__ void attn_kernel(const float* __restrict__ qkv, float* __restrict__ out)
{
    extern __shared__ float sm[];
    float* Ks = sm;
    float* Vs = sm + N * 64;
    const int bh = blockIdx.x;
    const int h = bh & 15;
    const int batch = bh >> 4;
    const float* base = qkv + (size_t)batch * N * 3072;
    const int tid = threadIdx.x;

    for (int idx = tid; idx < N * 16; idx += N) {
        const int j = idx >> 4, d4 = idx & 15;
        const float4* kp = reinterpret_cast<const float4*>(base + (size_t)j * 3072 + 1024 + h * 64);
        const float4* vp = reinterpret_cast<const float4*>(base + (size_t)j * 3072 + 2048 + h * 64);
        reinterpret_cast<float4*>(Ks + j * 64)[d4] = kp[d4];
        reinterpret_cast<float4*>(Vs + j * 64)[d4] = vp[d4];
    }
    __syncthreads();

    float4 q[16];
    const float4* qp = reinterpret_cast<const float4*>(base + (size_t)tid * 3072 + h * 64);
    #pragma unroll
    for (int d = 0; d < 16; d++) q[d] = qp[d];

    float m = -1e30f;
    for (int j = 0; j < N; j++) {
        const float4* kr = reinterpret_cast<const float4*>(Ks + j * 64);
        float s = 0.f;
        #pragma unroll
        for (int d = 0; d < 16; d++) {
            const float4 kv = kr[d];
            s += q[d].x*kv.x + q[d].y*kv.y + q[d].z*kv.z + q[d].w*kv.w;
        }
        m = fmaxf(m, s);
    }

    float4 acc[16];
    #pragma unroll
    for (int d = 0; d < 16; d++) acc[d] = make_float4(0.f, 0.f, 0.f, 0.f);
    float sum = 0.f;
    for (int j = 0; j < N; j++) {
        const float4* kr = reinterpret_cast<const float4*>(Ks + j * 64);
        float s = 0.f;
        #pragma unroll
        for (int d = 0; d < 16; d++) {
            const float4 kv = kr[d];
            s += q[d].x*kv.x + q[d].y*kv.y + q[d].z*kv.z + q[d].w*kv.w;
        }
        const float e = __expf(s - m);
        sum += e;
        const float4* vr = reinterpret_cast<const float4*>(Vs + j * 64);
        #pragma unroll
        for (int d = 0; d < 16; d++) {
            const float4 vv = vr[d];
            acc[d].x += e * vv.x; acc[d].y += e * vv.y;
            acc[d].z += e * vv.z; acc[d].w += e * vv.w;
        }
    }
    const float inv = 1.f / sum;
    float4* op = reinterpret_cast<float4*>(out + ((size_t)batch * N + tid) * 1024 + h * 64);
    #pragma unroll
    for (int d = 0; d < 16; d++)
        op[d] = make_float4(to_tf32(acc[d].x * inv), to_tf32(acc[d].y * inv),
                            to_tf32(acc[d].z * inv), to_tf32(acc[d].w * inv));
}

// ============================================================
// (B,T,S,C) <-> (B,S,T,C) row permutation
// ============================================================
__global__ void permute_kernel(const float* __restrict__ src, float* __restrict__ dst, int fwd)
{
    const int rt = blockIdx.x;
    int in_row;
    if (fwd) {
        const int t = rt & 15;  const int bs = rt >> 4;
        const int s = bs & 255; const int b  = bs >> 8;
        in_row = (b * 16 + t) * 256 + s;
    } else {
        const int s = rt & 255; const int bt = rt >> 8;
        const int t = bt & 15;  const int b  = bt >> 4;
        in_row = (b * 256 + s) * 16 + t;
    }
    const float4* sp = reinterpret_cast<const float4*>(src + (size_t)in_row * 1024);
    float4* dp = reinterpret_cast<float4*>(dst + (size_t)rt * 1024);
    dp[threadIdx.x] = sp[threadIdx.x];
}

// ============================================================
// Tensor-core GEMM via mma.sync (tf32):
//   C[M,N] = A[M,K] @ Bt[N,K]^T  (+bias)(+resid)(+gelu)(+round)
// 128x128 tile per CTA, BK=32, double-buffered cp.async.
// 8 warps in 4(M) x 2(N): warp tile 32x64 = 2x8 m16n8k8 tiles.
// Smem stride 36 floats -> conflict-free fragment LDS.
// ============================================================
constexpr int LDS_ = 36;                    // floats per row
constexpr int TILE_F = 128 * LDS_;          // floats per tile buffer
constexpr int GEMM_SMEM = 2 * 2 * TILE_F * 4;  // 73728 B

template<bool GELU, bool ROUND>
__global__ __launch_bounds__(256, 2) void gemm_mma(
    const float* __restrict__ A, const float* __restrict__ Bt,
    float* __restrict__ Cm, const float* __restrict__ bias,
    const float* __restrict__ resid, int M, int N, int K)
{
    extern __shared__ float sm[];
    float* As = sm;                 // [2][128][36]
    float* Bs = sm + 2 * TILE_F;    // [2][128][36]

    const int tid = threadIdx.x;
    const int wid = tid >> 5, lane = tid & 31;
    const int g = lane >> 2, tig = lane & 3;     // mma fragment coords
    const int warpM = wid & 3, warpN = wid >> 2; // 4x2 warp grid
    const int bx = blockIdx.x, by = blockIdx.y;
    const int NKB = K >> 5;

    // cp.async assignments: 4 chunks of 16B each for A and B
    uint32_t a_s[4], b_s[4];
    const float *a_g[4], *b_g[4];
    #pragma unroll
    for (int t = 0; t < 4; t++) {
        const int idx = tid + (t << 8);          // 0..1023
        const int r = idx >> 3, c = idx & 7;     // row, 16B chunk
        a_s[t] = smem_u32(As + r * LDS_ + c * 4);
        b_s[t] = smem_u32(Bs + r * LDS_ + c * 4);
        a_g[t] = A  + (size_t)(by * 128 + r) * K + c * 4;
        b_g[t] = Bt + (size_t)(bx * 128 + r) * K + c * 4;
    }

    auto load_stage = [&](int buf, int kb) {
        const uint32_t so = (uint32_t)(buf * TILE_F * 4);
        const int ko = kb << 5;
        #pragma unroll
        for (int t = 0; t < 4; t++)
            asm volatile("cp.async.cg.shared.global [%0], [%1], 16;" ::
                "r"(a_s[t] + so), "l"(a_g[t] + ko) : "memory");
        #pragma unroll
        for (int t = 0; t < 4; t++)
            asm volatile("cp.async.cg.shared.global [%0], [%1], 16;" ::
                "r"(b_s[t] + so), "l"(b_g[t] + ko) : "memory");
    };

    float acc[2][8][4];
    #pragma unroll
    for (int mt = 0; mt < 2; mt++)
        #pragma unroll
        for (int nt = 0; nt < 8; nt++)
            #pragma unroll
            for (int i = 0; i < 4; i++) acc[mt][nt][i] = 0.f;

    load_stage(0, 0);
    asm volatile("cp.async.commit_group;" ::: "memory");

    const int arow = warpM * 32 + g;         // + mt*16 (+8)
    const int brow = warpN * 64 + g;         // + nt*8

    for (int kb = 0; kb < NKB; kb++) {
        if (kb + 1 < NKB) {
            load_stage((kb + 1) & 1, kb + 1);
            asm volatile("cp.async.commit_group;" ::: "memory");
            asm volatile("cp.async.wait_group 1;" ::: "memory");
        } else {
            asm volatile("cp.async.wait_group 0;" ::: "memory");
        }
        __syncthreads();

        const float* Ab = As + (kb & 1) * TILE_F;
        const float* Bb = Bs + (kb & 1) * TILE_F;
        #pragma unroll
        for (int ks = 0; ks < 4; ks++) {
            const int k0 = ks * 8 + tig;
            uint32_t a[2][4], b[8][2];
            #pragma unroll
            for (int mt = 0; mt < 2; mt++) {
                const float* p = Ab + (arow + mt * 16) * LDS_ + k0;
                a[mt][0] = __float_as_uint(p[0]);
                a[mt][1] = __float_as_uint(p[8 * LDS_]);
                a[mt][2] = __float_as_uint(p[4]);
                a[mt][3] = __float_as_uint(p[8 * LDS_ + 4]);
            }
            #pragma unroll
            for (int nt = 0; nt < 8; nt++) {
                const float* p = Bb + (brow + nt * 8) * LDS_ + k0;
                b[nt][0] = __float_as_uint(p[0]);
                b[nt][1] = __float_as_uint(p[4]);
            }
            #pragma unroll
            for (int mt = 0; mt < 2; mt++)
                #pragma unroll
                for (int nt = 0; nt < 8; nt++)
                    mma_tf32(acc[mt][nt], a[mt], b[nt]);
        }
        __syncthreads();
    }

    // ---- epilogue ----
    #pragma unroll
    for (int mt = 0; mt < 2; mt++) {
        #pragma unroll
        for (int half = 0; half < 2; half++) {
            const int row = by * 128 + warpM * 32 + mt * 16 + g + half * 8;
            float* cp = Cm + (size_t)row * N;
            const float* rp = resid ? resid + (size_t)row * N : nullptr;
            #pragma unroll
            for (int nt = 0; nt < 8; nt++) {
                const int col = bx * 128 + warpN * 64 + nt * 8 + tig * 2;
                float v0 = acc[mt][nt][half * 2 + 0];
                float v1 = acc[mt][nt][half * 2 + 1];
                if (bias) { v0 += bias[col]; v1 += bias[col + 1]; }
                if (rp)   { v0 += rp[col];   v1 += rp[col + 1]; }
                if (GELU) {
                    v0 = 0.5f * v0 * (1.f + erff(v0 * 0.70710678f));
                    v1 = 0.5f * v1 * (1.f + erff(v1 * 0.70710678f));
                }
                if (ROUND) { v0 = to_tf32(v0); v1 = to_tf32(v1); }
                float2 v; v.x = v0; v.y = v1;
                *reinterpret_cast<float2*>(cp + col) = v;
            }
        }
    }
}

// ============================================================
extern "C" void kernel_launch(void* const* d_in, const int* /*in_sizes*/, int /*n_in*/,
                              void* d_out, int /*out_size*/)
{
    const float* x        = (const float*)d_in[0];
    const float* ns_w     = (const float*)d_in[1];
    const float* ns_b     = (const float*)d_in[2];
    const float* nt_w     = (const float*)d_in[3];
    const float* nt_b     = (const float*)d_in[4];
    const float* nm_w     = (const float*)d_in[5];
    const float* nm_b     = (const float*)d_in[6];
    const float* s_qkv    = (const float*)d_in[7];
    const float* s_qkn_w  = (const float*)d_in[8];
    const float* s_qkn_b  = (const float*)d_in[9];
    const float* s_proj_w = (const float*)d_in[10];
    const float* s_proj_b = (const float*)d_in[11];
    const float* t_qkv    = (const float*)d_in[12];
    const float* t_qkn_w  = (const float*)d_in[13];
    const float* t_qkn_b  = (const float*)d_in[14];
    const float* t_proj_w = (const float*)d_in[15];
    const float* t_proj_b = (const float*)d_in[16];
    const float* fc1_w    = (const float*)d_in[17];
    const float* fc1_b    = (const float*)d_in[18];
    const float* fc2_w    = (const float*)d_in[19];
    const float* fc2_b    = (const float*)d_in[20];
    float* out = (float*)d_out;

    float *xbuf, *xln, *qkv, *attn, *xt, *hbuf;
    float *wt_sqkv, *wt_sproj, *wt_tqkv, *wt_tproj, *wt_fc1, *wt_fc2;
    cudaGetSymbolAddress((void**)&xbuf, g_xbuf);
    cudaGetSymbolAddress((void**)&xln,  g_xln);
    cudaGetSymbolAddress((void**)&qkv,  g_qkv);
    cudaGetSymbolAddress((void**)&attn, g_attn);
    cudaGetSymbolAddress((void**)&xt,   g_xt);
    cudaGetSymbolAddress((void**)&hbuf, g_h);
    cudaGetSymbolAddress((void**)&wt_sqkv,  g_wt_sqkv);
    cudaGetSymbolAddress((void**)&wt_sproj, g_wt_sproj);
    cudaGetSymbolAddress((void**)&wt_tqkv,  g_wt_tqkv);
    cudaGetSymbolAddress((void**)&wt_tproj, g_wt_tproj);
    cudaGetSymbolAddress((void**)&wt_fc1,   g_wt_fc1);
    cudaGetSymbolAddress((void**)&wt_fc2,   g_wt_fc2);

    cudaFuncSetAttribute(attn_kernel<256>, cudaFuncAttributeMaxDynamicSharedMemorySize,
                         256 * 64 * 2 * (int)sizeof(float));
    cudaFuncSetAttribute(gemm_mma<false, false>, cudaFuncAttributeMaxDynamicSharedMemorySize, GEMM_SMEM);
    cudaFuncSetAttribute(gemm_mma<true,  true >, cudaFuncAttributeMaxDynamicSharedMemorySize, GEMM_SMEM);

    // ---- weight transposes (+ tf32 rounding), once per launch ----
    dim3 tb(32, 8);
    transpose_w<<<dim3(3072/32, 1024/32), tb>>>(s_qkv,    wt_sqkv,  1024, 3072);
    transpose_w<<<dim3(1024/32, 1024/32), tb>>>(s_proj_w, wt_sproj, 1024, 1024);
    transpose_w<<<dim3(3072/32, 1024/32), tb>>>(t_qkv,    wt_tqkv,  1024, 3072);
    transpose_w<<<dim3(1024/32, 1024/32), tb>>>(t_proj_w, wt_tproj, 1024, 1024);
    transpose_w<<<dim3(4096/32, 1024/32), tb>>>(fc1_w,    wt_fc1,   1024, 4096);
    transpose_w<<<dim3(1024/32, 4096/32), tb>>>(fc2_w,    wt_fc2,   4096, 1024);

    const int hl_blocks = (R_ * 2 * H_) / 8;

    // ---- spatial attention block ----
    ln_kernel<<<R_, 256>>>(x, xln, ns_w, ns_b);
    gemm_mma<false, false><<<dim3(24, 64), 256, GEMM_SMEM>>>(xln, wt_sqkv, qkv, nullptr, nullptr, R_, 3072, 1024);
    headln_kernel<<<hl_blocks, 256>>>(qkv, s_qkn_w, s_qkn_b, SCALE_);
    attn_kernel<256><<<B_ * T_ * H_, 256, 256 * 64 * 2 * sizeof(float)>>>(qkv, attn);
    gemm_mma<false, false><<<dim3(8, 64), 256, GEMM_SMEM>>>(attn, wt_sproj, xbuf, s_proj_b, x, R_, 1024, 1024);

    // ---- temporal attention block ----
    permute_kernel<<<R_, 256>>>(xbuf, xt, 1);
    ln_kernel<<<R_, 256>>>(xt, xln, nt_w, nt_b);
    gemm_mma<false, false><<<dim3(24, 64), 256, GEMM_SMEM>>>(xln, wt_tqkv, qkv, nullptr, nullptr, R_, 3072, 1024);
    headln_kernel<<<hl_blocks, 256>>>(qkv, t_qkn_w, t_qkn_b, SCALE_);
    attn_kernel<16><<<B_ * S_ * H_, 16, 16 * 64 * 2 * sizeof(float)>>>(qkv, attn);
    gemm_mma<false, false><<<dim3(8, 64), 256, GEMM_SMEM>>>(attn, wt_tproj, xln, t_proj_b, xt, R_, 1024, 1024);
    permute_kernel<<<R_, 256>>>(xln, xbuf, 0);

    // ---- MLP ----
    ln_kernel<<<R_, 256>>>(xbuf, xln, nm_w, nm_b);
    gemm_mma<true,  true ><<<dim3(32, 64), 256, GEMM_SMEM>>>(xln, wt_fc1, hbuf, fc1_b, nullptr, R_, 4096, 1024);
    gemm_mma<false, false><<<dim3(8, 64), 256, GEMM_SMEM>>>(hbuf, wt_fc2, out, fc2_b, xbuf, R_, 1024, 4096);
}